// round 6
// baseline (speedup 1.0000x reference)
#include <cuda_runtime.h>
#include <cuda_bf16.h>

#define H     2048
#define G4    8192          // 4*H gate rows
#define V     28
#define T     512
#define NCTA  148
#define CPB   14            // h-indices per CTA
#define ROWS  56            // gate rows per CTA
#define WMAT  16777216      // G4*H elements per matrix

// dynamic smem layout
//   uint2 s_w[49][512]   (200704 B)  -- int16 weights, 49 resident rows
//   float s_part[224]                -- 56 rows x 4 k-slice partials
//   float s_c[14]
// heads section reuses the s_w area as float s_h[2048].
#define SW_U2        (49 * 512)
#define OFF_PART_F   (SW_U2 * 2)
#define OFF_C_F      (OFF_PART_F + 224)
#define SMEM_FLOATS  (OFF_C_F + CPB)
#define SMEM_BYTES   (SMEM_FLOATS * 4)

// ---- device scratch (no allocations allowed) ----
__device__ float    g_table[2u * V * G4];   // [enc/dec][vocab][4H] gate table
__device__ short    g_Wq[2][WMAT];          // int16-quantized Whh
__device__ float    g_wscale[2][G4];        // per-row dequant scales
__device__ float    g_h[2][H];              // double-buffered hidden state
__device__ volatile unsigned g_arrive[NCTA];// per-CTA barrier stamps

__device__ __forceinline__ float warpsum(float v) {
#pragma unroll
    for (int o = 16; o; o >>= 1) v += __shfl_xor_sync(0xffffffffu, v, o);
    return v;
}
__device__ __forceinline__ float sigm(float x) { return 1.0f / (1.0f + expf(-x)); }

// All-to-all flag barrier. Each CTA stamps its own slot; warp 0 of every CTA
// polls all slots. Stamps are monotonic (wrap-safe compare); they persist
// across launches, so each launch derives its base from its own slot.
__device__ __forceinline__ void gbar(unsigned stamp, int lane, int w) {
    __syncthreads();                       // all CTA stores program-complete
    if (threadIdx.x == 0) {
        __threadfence();                   // release prior global stores
        g_arrive[blockIdx.x] = stamp;      // volatile store -> L2
    }
    if (w == 0) {
        bool ok;
        do {
            unsigned good = 1u;
#pragma unroll
            for (int i = 0; i < 5; i++) {
                int idx = lane + i * 32;
                if (idx < NCTA) {
                    unsigned v = g_arrive[idx];
                    good &= (unsigned)((int)(v - stamp) >= 0);
                }
            }
            ok = __all_sync(0xffffffffu, good != 0);
        } while (!ok);
        __threadfence();                   // acquire side
    }
    __syncthreads();                       // HB to all threads in CTA
}

// ---------------------------------------------------------------------------
// Quantize Whh rows to int16 with per-row fp32 scale.
// ---------------------------------------------------------------------------
__global__ __launch_bounds__(256) void k_quant(
    const float* __restrict__ encW, const float* __restrict__ decW)
{
    __shared__ float s_max[8];
    const int r     = blockIdx.x;       // 0..16383
    const int which = r >> 13;
    const int row   = r & (G4 - 1);
    const int tid = threadIdx.x, lane = tid & 31, w = tid >> 5;

    const float4* W4 = reinterpret_cast<const float4*>(
        (which ? decW : encW) + (size_t)row * H);

    float4 v0 = __ldg(&W4[tid]);
    float4 v1 = __ldg(&W4[tid + 256]);

    float m = fmaxf(fmaxf(fabsf(v0.x), fabsf(v0.y)), fmaxf(fabsf(v0.z), fabsf(v0.w)));
    m = fmaxf(m, fmaxf(fmaxf(fabsf(v1.x), fabsf(v1.y)), fmaxf(fabsf(v1.z), fabsf(v1.w))));
#pragma unroll
    for (int o = 16; o; o >>= 1) m = fmaxf(m, __shfl_xor_sync(0xffffffffu, m, o));
    if (lane == 0) s_max[w] = m;
    __syncthreads();
    if (tid == 0) {
        float mm = s_max[0];
#pragma unroll
        for (int i = 1; i < 8; i++) mm = fmaxf(mm, s_max[i]);
        s_max[0] = mm;
        g_wscale[which][row] = mm * (1.0f / 32766.0f);
    }
    __syncthreads();
    const float mv  = s_max[0];
    const float inv = (mv > 0.0f) ? (32766.0f / mv) : 0.0f;

    short4* Q4 = reinterpret_cast<short4*>(&g_Wq[which][(size_t)row * H]);
    short4 q;
    q.x = (short)__float2int_rn(v0.x * inv);
    q.y = (short)__float2int_rn(v0.y * inv);
    q.z = (short)__float2int_rn(v0.z * inv);
    q.w = (short)__float2int_rn(v0.w * inv);
    Q4[tid] = q;
    q.x = (short)__float2int_rn(v1.x * inv);
    q.y = (short)__float2int_rn(v1.y * inv);
    q.z = (short)__float2int_rn(v1.z * inv);
    q.w = (short)__float2int_rn(v1.w * inv);
    Q4[tid + 256] = q;
}

// ---------------------------------------------------------------------------
// Precompute per-vocab gate tables; block 0 also zeroes g_h[0].
// ---------------------------------------------------------------------------
__global__ __launch_bounds__(256) void k_pre(
    const float* __restrict__ enc_emb, const float* __restrict__ enc_Wih,
    const float* __restrict__ enc_bih, const float* __restrict__ enc_bhh,
    const float* __restrict__ dec_emb, const float* __restrict__ dec_Wih,
    const float* __restrict__ dec_bih, const float* __restrict__ dec_bhh)
{
    __shared__ __align__(16) float s_emb[V][256];
    const int tid = threadIdx.x, lane = tid & 31, warp = tid >> 5;

    if (blockIdx.x == 0) {
        for (int j = tid; j < H; j += 256) g_h[0][j] = 0.0f;
    }

    const int   which = (blockIdx.x >= 1024) ? 1 : 0;
    const float* emb = which ? dec_emb : enc_emb;
    const float* Wih = which ? dec_Wih : enc_Wih;
    const float* bih = which ? dec_bih : enc_bih;
    const float* bhh = which ? dec_bhh : enc_bhh;
    const int row = (blockIdx.x & 1023) * 8 + warp;   // 0..8191

    float acc[V];
#pragma unroll
    for (int v = 0; v < V; v++) acc[v] = 0.0f;

    for (int kt = 0; kt < 8; kt++) {
        const int k0 = kt * 256;
        __syncthreads();
        for (int idx = tid; idx < V * 256; idx += 256) {
            int v = idx >> 8, kk = idx & 255;
            s_emb[v][kk] = __ldg(&emb[v * H + k0 + kk]);
        }
        __syncthreads();
        const float4* Wr = reinterpret_cast<const float4*>(Wih + (size_t)row * H + k0);
#pragma unroll
        for (int it = 0; it < 2; it++) {
            const int kl = it * 32 + lane;
            float4 w4 = __ldg(&Wr[kl]);
#pragma unroll
            for (int v = 0; v < V; v++) {
                float4 e = reinterpret_cast<const float4*>(s_emb[v])[kl];
                acc[v] += w4.x * e.x + w4.y * e.y + w4.z * e.z + w4.w * e.w;
            }
        }
    }

    float bias = 0.0f;
#pragma unroll
    for (int v = 0; v < V; v++) {
        float s = warpsum(acc[v]);
        if (lane == 0) {
            if (v == 0) bias = __ldg(&bih[row]) + __ldg(&bhh[row]);
            g_table[(size_t)which * V * G4 + (size_t)v * G4 + row] = s + bias;
        }
    }
}

// ---------------------------------------------------------------------------
// Persistent LSTM kernel. 148 CTAs x 1024 threads.
// 32 warps = 8 row-groups (g) x 4 k-slices (q). Warp (g,q) handles rows
// lr = g + 8k (k=0..6) over h-slice [q*512, q*512+512). Rows lr<48 and lr=48
// live in SMEM; rows 49..55 (one per group g>=1) stream from L2 (prefetched).
// h is read directly into registers from g_h (no smem staging).
// ---------------------------------------------------------------------------
__global__ __launch_bounds__(1024, 1) void k_main(
    const int*   __restrict__ x,      const int*   __restrict__ target,
    const float* __restrict__ eps,
    const float* __restrict__ mu_W,    const float* __restrict__ mu_b,
    const float* __restrict__ lv_W,    const float* __restrict__ lv_b,
    float* __restrict__ out)
{
    extern __shared__ __align__(16) unsigned s_dyn[];
    uint2* s_w    = reinterpret_cast<uint2*>(s_dyn);            // [49][512]
    float* s_part = reinterpret_cast<float*>(s_dyn) + OFF_PART_F; // [224]
    float* s_c    = reinterpret_cast<float*>(s_dyn) + OFF_C_F;    // [14]

    const int tid = threadIdx.x, lane = tid & 31, w = tid >> 5;
    const int g = w >> 2;        // row-group 0..7
    const int q = w & 3;         // k-slice 0..3
    const int j0 = blockIdx.x * CPB;
    int nloc = H - j0;
    if (nloc > CPB) nloc = CPB;
    if (nloc < 0)  nloc = 0;
    const int nrows = nloc * 4;

    if (tid < CPB) s_c[tid] = 0.0f;

    unsigned stamp = g_arrive[blockIdx.x];   // barrier base (persists across launches)
    int rb = 0;

    for (int phase = 0; phase < 2; phase++) {
        const short* Wq    = g_Wq[phase];
        const float* wsc   = g_wscale[phase];
        const float* table = g_table + (size_t)phase * V * G4;

        // ---- load the 49 SMEM-resident weight rows for this phase ----
        __syncthreads();
        {
            const unsigned* Wq32 = reinterpret_cast<const unsigned*>(Wq);
            unsigned* sw32 = reinterpret_cast<unsigned*>(s_w);
            for (int sidx = 0; sidx < 49; sidx++) {
                int lr = (sidx < 48) ? ((sidx / 6) + 8 * (sidx % 6)) : 48;
                if (lr < nrows) {
                    const int row = (lr & 3) * H + j0 + (lr >> 2);
                    sw32[sidx * 1024 + tid] = __ldg(&Wq32[(size_t)row * 1024 + tid]);
                }
            }
        }
        __syncthreads();

        for (int t = 0; t < T; t++) {
            // prefetch streamed row (one per group, g>=1)
            const int lrs = 48 + g;
            const bool do_stream = (g >= 1) && (lrs < nrows);
            uint2 pf[4];
            if (do_stream) {
                const int row = (lrs & 3) * H + j0 + (lrs >> 2);
                const uint2* gw = reinterpret_cast<const uint2*>(
                    Wq + (size_t)row * H) + q * 128 + lane;
#pragma unroll
                for (int c = 0; c < 4; c++) pf[c] = __ldg(&gw[c * 32]);
            }

            // h slice straight into registers (L2 loads; L1 stale-unsafe)
            const float4* gh4 = reinterpret_cast<const float4*>(g_h[rb]);
            float4 hv[4];
#pragma unroll
            for (int c = 0; c < 4; c++)
                hv[c] = __ldcg(&gh4[q * 128 + c * 32 + lane]);

            // SMEM rows: k = 0..5 (all g), plus k=6 for g==0
            const int kmax = (g == 0) ? 7 : 6;
#pragma unroll
            for (int k = 0; k < 7; k++) {
                if (k >= kmax) break;
                const int lr = g + 8 * k;
                if (lr < nrows) {
                    const int sidx = (k < 6) ? (g * 6 + k) : 48;
                    const uint2* wp = s_w + (size_t)sidx * 512 + q * 128 + lane;
                    float acc = 0.0f;
#pragma unroll
                    for (int c = 0; c < 4; c++) {
                        uint2 ab = wp[c * 32];
                        short2 p0 = *reinterpret_cast<short2*>(&ab.x);
                        short2 p1 = *reinterpret_cast<short2*>(&ab.y);
                        acc += (float)p0.x * hv[c].x + (float)p0.y * hv[c].y;
                        acc += (float)p1.x * hv[c].z + (float)p1.y * hv[c].w;
                    }
                    acc = warpsum(acc);
                    if (lane == 0) s_part[lr * 4 + q] = acc;
                }
            }
            if (do_stream) {
                float acc = 0.0f;
#pragma unroll
                for (int c = 0; c < 4; c++) {
                    short2 p0 = *reinterpret_cast<short2*>(&pf[c].x);
                    short2 p1 = *reinterpret_cast<short2*>(&pf[c].y);
                    acc += (float)p0.x * hv[c].x + (float)p0.y * hv[c].y;
                    acc += (float)p1.x * hv[c].z + (float)p1.y * hv[c].w;
                }
                acc = warpsum(acc);
                if (lane == 0) s_part[lrs * 4 + q] = acc;
            }
            __syncthreads();

            // fused combine + dequant + cell update by the 14 owner threads
            if (tid < nloc) {
                const int tok = (phase == 0) ? __ldg(&x[t])
                                             : (t == 0 ? 0 : __ldg(&target[t - 1]));
                float gate[4];
#pragma unroll
                for (int ga = 0; ga < 4; ga++) {
                    const int lr = tid * 4 + ga;
                    const int row = ga * H + j0 + tid;
                    float s = s_part[lr * 4 + 0] + s_part[lr * 4 + 1] +
                              s_part[lr * 4 + 2] + s_part[lr * 4 + 3];
                    gate[ga] = s * __ldg(&wsc[row]) +
                               __ldg(&table[(size_t)tok * G4 + row]);
                }
                float c = sigm(gate[1]) * s_c[tid] + sigm(gate[0]) * tanhf(gate[2]);
                s_c[tid] = c;
                float h = sigm(gate[3]) * tanhf(c);
                __stcg(&g_h[rb ^ 1][j0 + tid], h);
                if (phase)
                    out[512 + (size_t)t * H + j0 + tid] = h;
            }
            stamp++;
            gbar(stamp, lane, w);
            rb ^= 1;
        }

        if (phase == 0) {
            // VAE heads: stage h_enc into the (now reusable) weight area
            float* s_h = reinterpret_cast<float*>(s_dyn);
            __syncthreads();
            for (int j = tid; j < H; j += 1024) s_h[j] = __ldcg(&g_h[rb][j]);
            __syncthreads();
            const float4* sh4 = reinterpret_cast<const float4*>(s_h);
            if (w < nloc * 2) {
                const int l = w >> 1, m = w & 1;
                const float* Wm = m ? lv_W : mu_W;
                const int row = j0 + l;
                const float4* W4 = reinterpret_cast<const float4*>(Wm) +
                                   (size_t)row * (H / 4);
                float s = 0.0f;
#pragma unroll 8
                for (int i = lane; i < H / 4; i += 32) {
                    float4 a = __ldg(&W4[i]);
                    float4 b = sh4[i];
                    s += a.x * b.x + a.y * b.y + a.z * b.z + a.w * b.w;
                }
                s = warpsum(s);
                if (lane == 0)
                    s_part[w] = s + __ldg(&(m ? lv_b : mu_b)[row]);
            }
            __syncthreads();
            if (tid < nloc) {
                const int j = j0 + tid;
                const float mu = s_part[tid * 2 + 0];
                const float lv = s_part[tid * 2 + 1];
                out[512 + (size_t)T * H + j]     = mu;
                out[512 + (size_t)T * H + H + j] = lv;
                float z = mu + __ldg(&eps[j]) * expf(0.5f * lv);
                __stcg(&g_h[rb ^ 1][j], z);
            }
            stamp++;
            gbar(stamp, lane, w);
            rb ^= 1;
        }
    }
}

// ---------------------------------------------------------------------------
// Argmax over hidden dim of each decoder output row (first-index tie-break).
// ---------------------------------------------------------------------------
__global__ __launch_bounds__(256) void k_argmax(float* __restrict__ out)
{
    __shared__ float sv[256];
    __shared__ int   si[256];
    const int t = blockIdx.x;
    const float* row = out + 512 + (size_t)t * H;
    float best = -3.402823466e+38f;
    int   bi = 0;
    for (int j = threadIdx.x; j < H; j += 256) {
        float v = row[j];
        if (v > best) { best = v; bi = j; }
    }
    sv[threadIdx.x] = best;
    si[threadIdx.x] = bi;
    __syncthreads();
    for (int s = 128; s; s >>= 1) {
        if (threadIdx.x < s) {
            float ov = sv[threadIdx.x + s];
            int   oi = si[threadIdx.x + s];
            if (ov > sv[threadIdx.x] ||
                (ov == sv[threadIdx.x] && oi < si[threadIdx.x])) {
                sv[threadIdx.x] = ov;
                si[threadIdx.x] = oi;
            }
        }
        __syncthreads();
    }
    if (threadIdx.x == 0) out[t] = (float)si[0];
}

// ---------------------------------------------------------------------------
extern "C" void kernel_launch(void* const* d_in, const int* in_sizes, int n_in,
                              void* d_out, int out_size)
{
    const int*   x       = (const int*)  d_in[0];
    const int*   target  = (const int*)  d_in[1];
    const float* eps     = (const float*)d_in[2];
    const float* enc_emb = (const float*)d_in[3];
    const float* enc_Wih = (const float*)d_in[4];
    const float* enc_Whh = (const float*)d_in[5];
    const float* enc_bih = (const float*)d_in[6];
    const float* enc_bhh = (const float*)d_in[7];
    const float* mu_W    = (const float*)d_in[8];
    const float* mu_b    = (const float*)d_in[9];
    const float* lv_W    = (const float*)d_in[10];
    const float* lv_b    = (const float*)d_in[11];
    const float* dec_emb = (const float*)d_in[12];
    const float* dec_Wih = (const float*)d_in[13];
    const float* dec_Whh = (const float*)d_in[14];
    const float* dec_bih = (const float*)d_in[15];
    const float* dec_bhh = (const float*)d_in[16];
    float* out = (float*)d_out;

    cudaFuncSetAttribute(k_main, cudaFuncAttributeMaxDynamicSharedMemorySize,
                         SMEM_BYTES);

    k_pre<<<2048, 256>>>(enc_emb, enc_Wih, enc_bih, enc_bhh,
                         dec_emb, dec_Wih, dec_bih, dec_bhh);
    k_quant<<<2 * G4, 256>>>(enc_Whh, dec_Whh);
    k_main<<<NCTA, 1024, SMEM_BYTES>>>(x, target, eps,
                                       mu_W, mu_b, lv_W, lv_b, out);
    k_argmax<<<512, 256>>>(out);
}

// round 7
// speedup vs baseline: 1.4215x; 1.4215x over previous
#include <cuda_runtime.h>
#include <cuda_bf16.h>

#define H     2048
#define G4    8192          // 4*H gate rows
#define V     28
#define T     512
#define NCTA  148
#define CPB   14            // h-indices per CTA
#define ROWS  56            // gate rows per CTA
#define WMAT  16777216      // G4*H elements per matrix
#define NGRP  16

// dynamic smem layout
//   uint2 s_w[49][512]   (200704 B)  -- int16 weights, 49 resident rows
//   float s_part[224]                -- 56 rows x 4 k-slice partials
//   float s_c[14]
// heads section reuses the s_w area as float s_h[2048].
#define SW_U2        (49 * 512)
#define OFF_PART_F   (SW_U2 * 2)
#define OFF_C_F      (OFF_PART_F + 224)
#define SMEM_FLOATS  (OFF_C_F + CPB)
#define SMEM_BYTES   (SMEM_FLOATS * 4)

// ---- device scratch (no allocations allowed) ----
__device__ float    g_table[2u * V * G4];   // [enc/dec][vocab][4H] gate table
__device__ short    g_Wq[2][WMAT];          // int16-quantized Whh
__device__ float    g_wscale[2][G4];        // per-row dequant scales
__device__ float    g_h[2][H];              // double-buffered hidden state
// hierarchical barrier state (each live word on its own 128B line)
__device__ unsigned g_cnt1[NGRP * 32];      // per-group arrival counters (monotonic)
__device__ unsigned g_cnt_root;             // root arrival counter (monotonic)
__device__ volatile unsigned g_rel[NGRP * 32]; // per-group release epochs

__device__ __forceinline__ float warpsum(float v) {
#pragma unroll
    for (int o = 16; o; o >>= 1) v += __shfl_xor_sync(0xffffffffu, v, o);
    return v;
}
__device__ __forceinline__ float sigm(float x) { return 1.0f / (1.0f + expf(-x)); }

// 2-level tree barrier. Counters are zeroed by k_pre before k_main (stream
// order), so epochs start at 1 each launch. Only tid 0 touches global sync
// state: one fence, one atomic, one low-contention poll per CTA per step.
__device__ __forceinline__ void gbar(unsigned epoch, int grp, unsigned gsz) {
    __syncthreads();                           // CTA's h stores program-complete
    if (threadIdx.x == 0) {
        __threadfence();                       // release (cumulative via bar)
        unsigned a = atomicAdd(&g_cnt1[grp * 32], 1u);
        if (a == epoch * gsz - 1u) {           // last in group this epoch
            unsigned r = atomicAdd(&g_cnt_root, 1u);
            if (r == epoch * (unsigned)NGRP - 1u) {   // last overall
                __threadfence();
#pragma unroll
                for (int g2 = 0; g2 < NGRP; g2++) g_rel[g2 * 32] = epoch;
            }
        }
        while ((int)(g_rel[grp * 32] - epoch) < 0) { }
        __threadfence();                       // acquire
    }
    __syncthreads();
}

// ---------------------------------------------------------------------------
// Quantize Whh rows to int16 with per-row fp32 scale.
// ---------------------------------------------------------------------------
__global__ __launch_bounds__(256) void k_quant(
    const float* __restrict__ encW, const float* __restrict__ decW)
{
    __shared__ float s_max[8];
    const int r     = blockIdx.x;       // 0..16383
    const int which = r >> 13;
    const int row   = r & (G4 - 1);
    const int tid = threadIdx.x, lane = tid & 31, w = tid >> 5;

    const float4* W4 = reinterpret_cast<const float4*>(
        (which ? decW : encW) + (size_t)row * H);

    float4 v0 = __ldg(&W4[tid]);
    float4 v1 = __ldg(&W4[tid + 256]);

    float m = fmaxf(fmaxf(fabsf(v0.x), fabsf(v0.y)), fmaxf(fabsf(v0.z), fabsf(v0.w)));
    m = fmaxf(m, fmaxf(fmaxf(fabsf(v1.x), fabsf(v1.y)), fmaxf(fabsf(v1.z), fabsf(v1.w))));
#pragma unroll
    for (int o = 16; o; o >>= 1) m = fmaxf(m, __shfl_xor_sync(0xffffffffu, m, o));
    if (lane == 0) s_max[w] = m;
    __syncthreads();
    if (tid == 0) {
        float mm = s_max[0];
#pragma unroll
        for (int i = 1; i < 8; i++) mm = fmaxf(mm, s_max[i]);
        s_max[0] = mm;
        g_wscale[which][row] = mm * (1.0f / 32766.0f);
    }
    __syncthreads();
    const float mv  = s_max[0];
    const float inv = (mv > 0.0f) ? (32766.0f / mv) : 0.0f;

    short4* Q4 = reinterpret_cast<short4*>(&g_Wq[which][(size_t)row * H]);
    short4 q;
    q.x = (short)__float2int_rn(v0.x * inv);
    q.y = (short)__float2int_rn(v0.y * inv);
    q.z = (short)__float2int_rn(v0.z * inv);
    q.w = (short)__float2int_rn(v0.w * inv);
    Q4[tid] = q;
    q.x = (short)__float2int_rn(v1.x * inv);
    q.y = (short)__float2int_rn(v1.y * inv);
    q.z = (short)__float2int_rn(v1.z * inv);
    q.w = (short)__float2int_rn(v1.w * inv);
    Q4[tid + 256] = q;
}

// ---------------------------------------------------------------------------
// Precompute per-vocab gate tables; block 0 also zeroes g_h[0] and ALL
// barrier state (so k_main epochs restart at 1 on every graph replay).
// ---------------------------------------------------------------------------
__global__ __launch_bounds__(256) void k_pre(
    const float* __restrict__ enc_emb, const float* __restrict__ enc_Wih,
    const float* __restrict__ enc_bih, const float* __restrict__ enc_bhh,
    const float* __restrict__ dec_emb, const float* __restrict__ dec_Wih,
    const float* __restrict__ dec_bih, const float* __restrict__ dec_bhh)
{
    __shared__ __align__(16) float s_emb[V][256];
    const int tid = threadIdx.x, lane = tid & 31, warp = tid >> 5;

    if (blockIdx.x == 0) {
        for (int j = tid; j < H; j += 256) g_h[0][j] = 0.0f;
        for (int j = tid; j < NGRP * 32; j += 256) {
            g_cnt1[j] = 0u;
            g_rel[j]  = 0u;
        }
        if (tid == 0) g_cnt_root = 0u;
    }

    const int   which = (blockIdx.x >= 1024) ? 1 : 0;
    const float* emb = which ? dec_emb : enc_emb;
    const float* Wih = which ? dec_Wih : enc_Wih;
    const float* bih = which ? dec_bih : enc_bih;
    const float* bhh = which ? dec_bhh : enc_bhh;
    const int row = (blockIdx.x & 1023) * 8 + warp;   // 0..8191

    float acc[V];
#pragma unroll
    for (int v = 0; v < V; v++) acc[v] = 0.0f;

    for (int kt = 0; kt < 8; kt++) {
        const int k0 = kt * 256;
        __syncthreads();
        for (int idx = tid; idx < V * 256; idx += 256) {
            int v = idx >> 8, kk = idx & 255;
            s_emb[v][kk] = __ldg(&emb[v * H + k0 + kk]);
        }
        __syncthreads();
        const float4* Wr = reinterpret_cast<const float4*>(Wih + (size_t)row * H + k0);
#pragma unroll
        for (int it = 0; it < 2; it++) {
            const int kl = it * 32 + lane;
            float4 w4 = __ldg(&Wr[kl]);
#pragma unroll
            for (int v = 0; v < V; v++) {
                float4 e = reinterpret_cast<const float4*>(s_emb[v])[kl];
                acc[v] += w4.x * e.x + w4.y * e.y + w4.z * e.z + w4.w * e.w;
            }
        }
    }

    float bias = 0.0f;
#pragma unroll
    for (int v = 0; v < V; v++) {
        float s = warpsum(acc[v]);
        if (lane == 0) {
            if (v == 0) bias = __ldg(&bih[row]) + __ldg(&bhh[row]);
            g_table[(size_t)which * V * G4 + (size_t)v * G4 + row] = s + bias;
        }
    }
}

// ---------------------------------------------------------------------------
// Persistent LSTM kernel. 148 CTAs x 1024 threads.
// 32 warps = 8 row-groups (g) x 4 k-slices (q). Warp (g,q) handles rows
// lr = g + 8k (k=0..6) over h-slice [q*512, q*512+512). Rows lr<48 and lr=48
// live in SMEM; rows 49..55 (one per group g>=1) stream from L2 (prefetched).
// h is read directly into registers from g_h. Sync = gbar (2-level tree).
// ---------------------------------------------------------------------------
__global__ __launch_bounds__(1024, 1) void k_main(
    const int*   __restrict__ x,      const int*   __restrict__ target,
    const float* __restrict__ eps,
    const float* __restrict__ mu_W,    const float* __restrict__ mu_b,
    const float* __restrict__ lv_W,    const float* __restrict__ lv_b,
    float* __restrict__ out)
{
    extern __shared__ __align__(16) unsigned s_dyn[];
    uint2* s_w    = reinterpret_cast<uint2*>(s_dyn);              // [49][512]
    float* s_part = reinterpret_cast<float*>(s_dyn) + OFF_PART_F; // [224]
    float* s_c    = reinterpret_cast<float*>(s_dyn) + OFF_C_F;    // [14]

    const int tid = threadIdx.x, lane = tid & 31, w = tid >> 5;
    const int g = w >> 2;        // row-group 0..7
    const int q = w & 3;         // k-slice 0..3
    const int j0 = blockIdx.x * CPB;
    int nloc = H - j0;
    if (nloc > CPB) nloc = CPB;
    if (nloc < 0)  nloc = 0;
    const int nrows = nloc * 4;

    // barrier group of this CTA: groups 0..3 have 10 CTAs, 4..15 have 9
    int grp; unsigned gsz;
    if (blockIdx.x < 40) { grp = blockIdx.x / 10;            gsz = 10u; }
    else                 { grp = 4 + (blockIdx.x - 40) / 9;  gsz = 9u;  }

    if (tid < CPB) s_c[tid] = 0.0f;

    unsigned epoch = 0;
    int rb = 0;

    for (int phase = 0; phase < 2; phase++) {
        const short* Wq    = g_Wq[phase];
        const float* wsc   = g_wscale[phase];
        const float* table = g_table + (size_t)phase * V * G4;

        // ---- load the 49 SMEM-resident weight rows for this phase ----
        __syncthreads();
        {
            const unsigned* Wq32 = reinterpret_cast<const unsigned*>(Wq);
            unsigned* sw32 = reinterpret_cast<unsigned*>(s_w);
            for (int sidx = 0; sidx < 49; sidx++) {
                int lr = (sidx < 48) ? ((sidx / 6) + 8 * (sidx % 6)) : 48;
                if (lr < nrows) {
                    const int row = (lr & 3) * H + j0 + (lr >> 2);
                    sw32[sidx * 1024 + tid] = __ldg(&Wq32[(size_t)row * 1024 + tid]);
                }
            }
        }
        __syncthreads();

        for (int t = 0; t < T; t++) {
            // prefetch streamed row (one per group, g>=1)
            const int lrs = 48 + g;
            const bool do_stream = (g >= 1) && (lrs < nrows);
            uint2 pf[4];
            if (do_stream) {
                const int row = (lrs & 3) * H + j0 + (lrs >> 2);
                const uint2* gw = reinterpret_cast<const uint2*>(
                    Wq + (size_t)row * H) + q * 128 + lane;
#pragma unroll
                for (int c = 0; c < 4; c++) pf[c] = __ldg(&gw[c * 32]);
            }

            // h slice straight into registers (L2 loads; L1 stale-unsafe)
            const float4* gh4 = reinterpret_cast<const float4*>(g_h[rb]);
            float4 hv[4];
#pragma unroll
            for (int c = 0; c < 4; c++)
                hv[c] = __ldcg(&gh4[q * 128 + c * 32 + lane]);

            // SMEM rows: k = 0..5 (all g), plus k=6 for g==0
            const int kmax = (g == 0) ? 7 : 6;
#pragma unroll
            for (int k = 0; k < 7; k++) {
                if (k >= kmax) break;
                const int lr = g + 8 * k;
                if (lr < nrows) {
                    const int sidx = (k < 6) ? (g * 6 + k) : 48;
                    const uint2* wp = s_w + (size_t)sidx * 512 + q * 128 + lane;
                    float acc = 0.0f;
#pragma unroll
                    for (int c = 0; c < 4; c++) {
                        uint2 ab = wp[c * 32];
                        short2 p0 = *reinterpret_cast<short2*>(&ab.x);
                        short2 p1 = *reinterpret_cast<short2*>(&ab.y);
                        acc += (float)p0.x * hv[c].x + (float)p0.y * hv[c].y;
                        acc += (float)p1.x * hv[c].z + (float)p1.y * hv[c].w;
                    }
                    acc = warpsum(acc);
                    if (lane == 0) s_part[lr * 4 + q] = acc;
                }
            }
            if (do_stream) {
                float acc = 0.0f;
#pragma unroll
                for (int c = 0; c < 4; c++) {
                    short2 p0 = *reinterpret_cast<short2*>(&pf[c].x);
                    short2 p1 = *reinterpret_cast<short2*>(&pf[c].y);
                    acc += (float)p0.x * hv[c].x + (float)p0.y * hv[c].y;
                    acc += (float)p1.x * hv[c].z + (float)p1.y * hv[c].w;
                }
                acc = warpsum(acc);
                if (lane == 0) s_part[lrs * 4 + q] = acc;
            }
            __syncthreads();

            // fused combine + dequant + cell update by the 14 owner threads
            if (tid < nloc) {
                const int tok = (phase == 0) ? __ldg(&x[t])
                                             : (t == 0 ? 0 : __ldg(&target[t - 1]));
                float gate[4];
#pragma unroll
                for (int ga = 0; ga < 4; ga++) {
                    const int lr = tid * 4 + ga;
                    const int row = ga * H + j0 + tid;
                    float s = s_part[lr * 4 + 0] + s_part[lr * 4 + 1] +
                              s_part[lr * 4 + 2] + s_part[lr * 4 + 3];
                    gate[ga] = s * __ldg(&wsc[row]) +
                               __ldg(&table[(size_t)tok * G4 + row]);
                }
                float c = sigm(gate[1]) * s_c[tid] + sigm(gate[0]) * tanhf(gate[2]);
                s_c[tid] = c;
                float h = sigm(gate[3]) * tanhf(c);
                __stcg(&g_h[rb ^ 1][j0 + tid], h);
                if (phase)
                    out[512 + (size_t)t * H + j0 + tid] = h;
            }
            epoch++;
            gbar(epoch, grp, gsz);
            rb ^= 1;
        }

        if (phase == 0) {
            // VAE heads: stage h_enc into the (now reusable) weight area
            float* s_h = reinterpret_cast<float*>(s_dyn);
            __syncthreads();
            for (int j = tid; j < H; j += 1024) s_h[j] = __ldcg(&g_h[rb][j]);
            __syncthreads();
            const float4* sh4 = reinterpret_cast<const float4*>(s_h);
            if (w < nloc * 2) {
                const int l = w >> 1, m = w & 1;
                const float* Wm = m ? lv_W : mu_W;
                const int row = j0 + l;
                const float4* W4 = reinterpret_cast<const float4*>(Wm) +
                                   (size_t)row * (H / 4);
                float s = 0.0f;
#pragma unroll 8
                for (int i = lane; i < H / 4; i += 32) {
                    float4 a = __ldg(&W4[i]);
                    float4 b = sh4[i];
                    s += a.x * b.x + a.y * b.y + a.z * b.z + a.w * b.w;
                }
                s = warpsum(s);
                if (lane == 0)
                    s_part[w] = s + __ldg(&(m ? lv_b : mu_b)[row]);
            }
            __syncthreads();
            if (tid < nloc) {
                const int j = j0 + tid;
                const float mu = s_part[tid * 2 + 0];
                const float lv = s_part[tid * 2 + 1];
                out[512 + (size_t)T * H + j]     = mu;
                out[512 + (size_t)T * H + H + j] = lv;
                float z = mu + __ldg(&eps[j]) * expf(0.5f * lv);
                __stcg(&g_h[rb ^ 1][j], z);
            }
            epoch++;
            gbar(epoch, grp, gsz);
            rb ^= 1;
        }
    }
}

// ---------------------------------------------------------------------------
// Argmax over hidden dim of each decoder output row (first-index tie-break).
// ---------------------------------------------------------------------------
__global__ __launch_bounds__(256) void k_argmax(float* __restrict__ out)
{
    __shared__ float sv[256];
    __shared__ int   si[256];
    const int t = blockIdx.x;
    const float* row = out + 512 + (size_t)t * H;
    float best = -3.402823466e+38f;
    int   bi = 0;
    for (int j = threadIdx.x; j < H; j += 256) {
        float v = row[j];
        if (v > best) { best = v; bi = j; }
    }
    sv[threadIdx.x] = best;
    si[threadIdx.x] = bi;
    __syncthreads();
    for (int s = 128; s; s >>= 1) {
        if (threadIdx.x < s) {
            float ov = sv[threadIdx.x + s];
            int   oi = si[threadIdx.x + s];
            if (ov > sv[threadIdx.x] ||
                (ov == sv[threadIdx.x] && oi < si[threadIdx.x])) {
                sv[threadIdx.x] = ov;
                si[threadIdx.x] = oi;
            }
        }
        __syncthreads();
    }
    if (threadIdx.x == 0) out[t] = (float)si[0];
}

// ---------------------------------------------------------------------------
extern "C" void kernel_launch(void* const* d_in, const int* in_sizes, int n_in,
                              void* d_out, int out_size)
{
    const int*   x       = (const int*)  d_in[0];
    const int*   target  = (const int*)  d_in[1];
    const float* eps     = (const float*)d_in[2];
    const float* enc_emb = (const float*)d_in[3];
    const float* enc_Wih = (const float*)d_in[4];
    const float* enc_Whh = (const float*)d_in[5];
    const float* enc_bih = (const float*)d_in[6];
    const float* enc_bhh = (const float*)d_in[7];
    const float* mu_W    = (const float*)d_in[8];
    const float* mu_b    = (const float*)d_in[9];
    const float* lv_W    = (const float*)d_in[10];
    const float* lv_b    = (const float*)d_in[11];
    const float* dec_emb = (const float*)d_in[12];
    const float* dec_Wih = (const float*)d_in[13];
    const float* dec_Whh = (const float*)d_in[14];
    const float* dec_bih = (const float*)d_in[15];
    const float* dec_bhh = (const float*)d_in[16];
    float* out = (float*)d_out;

    cudaFuncSetAttribute(k_main, cudaFuncAttributeMaxDynamicSharedMemorySize,
                         SMEM_BYTES);

    k_pre<<<2048, 256>>>(enc_emb, enc_Wih, enc_bih, enc_bhh,
                         dec_emb, dec_Wih, dec_bih, dec_bhh);
    k_quant<<<2 * G4, 256>>>(enc_Whh, dec_Whh);
    k_main<<<NCTA, 1024, SMEM_BYTES>>>(x, target, eps,
                                       mu_W, mu_b, lv_W, lv_b, out);
    k_argmax<<<512, 256>>>(out);
}

// round 8
// speedup vs baseline: 1.8161x; 1.2777x over previous
#include <cuda_runtime.h>
#include <cuda_bf16.h>

#define H     2048
#define G4    8192          // 4*H gate rows
#define V     28
#define T     512
#define NCTA  148
#define CPB   14            // h-indices per CTA
#define ROWS  56            // gate rows per CTA
#define SMEM_ROWS 49        // rows resident in SMEM; rest (7) stream from L2
#define WMAT  16777216      // G4*H elements per matrix
#define KMAGIC 8421376.0f   // 2^23 + 32768 (biased-u16 float offset)

// dynamic smem layout (u32 units)
#define OFF_W     0
#define OFF_H     (SMEM_ROWS * 1024)            // 50176
#define OFF_PART  (OFF_H + 2048)                // 52224  : 56 rows x 4 slices
#define OFF_GATES (OFF_PART + ROWS * 4)         // 52448
#define OFF_C     (OFF_GATES + ROWS)            // 52504
#define SMEM_U32  (OFF_C + CPB)                 // 52518
#define SMEM_BYTES (SMEM_U32 * 4)               // 210072

// ---- device scratch (no allocations allowed) ----
__device__ float          g_table[2u * V * G4]; // [enc/dec][vocab][4H] gate table
__device__ unsigned short g_Wq[2][WMAT];        // biased-u16 quantized Whh
__device__ float          g_wscale[2][G4];      // per-row dequant scales
__device__ float          g_h[2][H];            // double-buffered hidden state
__device__ unsigned       g_bar_count = 0;
__device__ unsigned       g_bar_phase = 0;

__device__ __forceinline__ float warpsum(float v) {
#pragma unroll
    for (int o = 16; o; o >>= 1) v += __shfl_xor_sync(0xffffffffu, v, o);
    return v;
}
__device__ __forceinline__ float sigm(float x) { return 1.0f / (1.0f + expf(-x)); }

// Counter grid barrier (measured best in rounds 3-7). All NCTA CTAs co-resident.
__device__ __forceinline__ void grid_sync() {
    __syncthreads();
    if (threadIdx.x == 0) {
        volatile unsigned* ph = &g_bar_phase;
        unsigned p = *ph;
        __threadfence();
        unsigned arr = atomicAdd(&g_bar_count, 1u);
        if (arr == NCTA - 1u) {
            g_bar_count = 0u;
            __threadfence();
            atomicAdd(&g_bar_phase, 1u);
        } else {
            while (*ph == p) { }
            __threadfence();
        }
    }
    __syncthreads();
}

// biased-u16 pair -> 2 fp32 (value = 2^23 + biased) via PRMT; no I2F.
#define CVT_LO(u) __uint_as_float(__byte_perm((u), 0x4B000000u, 0x7410))
#define CVT_HI(u) __uint_as_float(__byte_perm((u), 0x4B000000u, 0x7432))

// ---------------------------------------------------------------------------
// Quantize Whh rows to biased uint16 with per-row fp32 scale.
// ---------------------------------------------------------------------------
__global__ __launch_bounds__(256) void k_quant(
    const float* __restrict__ encW, const float* __restrict__ decW)
{
    __shared__ float s_max[8];
    const int r     = blockIdx.x;       // 0..16383
    const int which = r >> 13;
    const int row   = r & (G4 - 1);
    const int tid = threadIdx.x, lane = tid & 31, w = tid >> 5;

    const float4* W4 = reinterpret_cast<const float4*>(
        (which ? decW : encW) + (size_t)row * H);

    float4 v0 = __ldg(&W4[tid]);
    float4 v1 = __ldg(&W4[tid + 256]);

    float m = fmaxf(fmaxf(fabsf(v0.x), fabsf(v0.y)), fmaxf(fabsf(v0.z), fabsf(v0.w)));
    m = fmaxf(m, fmaxf(fmaxf(fabsf(v1.x), fabsf(v1.y)), fmaxf(fabsf(v1.z), fabsf(v1.w))));
#pragma unroll
    for (int o = 16; o; o >>= 1) m = fmaxf(m, __shfl_xor_sync(0xffffffffu, m, o));
    if (lane == 0) s_max[w] = m;
    __syncthreads();
    if (tid == 0) {
        float mm = s_max[0];
#pragma unroll
        for (int i = 1; i < 8; i++) mm = fmaxf(mm, s_max[i]);
        s_max[0] = mm;
        g_wscale[which][row] = mm * (1.0f / 32766.0f);
    }
    __syncthreads();
    const float mv  = s_max[0];
    const float inv = (mv > 0.0f) ? (32766.0f / mv) : 0.0f;

    ushort4* Q4 = reinterpret_cast<ushort4*>(&g_Wq[which][(size_t)row * H]);
    ushort4 q;
    q.x = (unsigned short)(__float2int_rn(v0.x * inv) + 32768);
    q.y = (unsigned short)(__float2int_rn(v0.y * inv) + 32768);
    q.z = (unsigned short)(__float2int_rn(v0.z * inv) + 32768);
    q.w = (unsigned short)(__float2int_rn(v0.w * inv) + 32768);
    Q4[tid] = q;
    q.x = (unsigned short)(__float2int_rn(v1.x * inv) + 32768);
    q.y = (unsigned short)(__float2int_rn(v1.y * inv) + 32768);
    q.z = (unsigned short)(__float2int_rn(v1.z * inv) + 32768);
    q.w = (unsigned short)(__float2int_rn(v1.w * inv) + 32768);
    Q4[tid + 256] = q;
}

// ---------------------------------------------------------------------------
// Precompute per-vocab gate tables; block 0 also zeroes g_h[0].
// ---------------------------------------------------------------------------
__global__ __launch_bounds__(256) void k_pre(
    const float* __restrict__ enc_emb, const float* __restrict__ enc_Wih,
    const float* __restrict__ enc_bih, const float* __restrict__ enc_bhh,
    const float* __restrict__ dec_emb, const float* __restrict__ dec_Wih,
    const float* __restrict__ dec_bih, const float* __restrict__ dec_bhh)
{
    __shared__ __align__(16) float s_emb[V][256];
    const int tid = threadIdx.x, lane = tid & 31, warp = tid >> 5;

    if (blockIdx.x == 0) {
        for (int j = tid; j < H; j += 256) g_h[0][j] = 0.0f;
    }

    const int   which = (blockIdx.x >= 1024) ? 1 : 0;
    const float* emb = which ? dec_emb : enc_emb;
    const float* Wih = which ? dec_Wih : enc_Wih;
    const float* bih = which ? dec_bih : enc_bih;
    const float* bhh = which ? dec_bhh : enc_bhh;
    const int row = (blockIdx.x & 1023) * 8 + warp;   // 0..8191

    float acc[V];
#pragma unroll
    for (int v = 0; v < V; v++) acc[v] = 0.0f;

    for (int kt = 0; kt < 8; kt++) {
        const int k0 = kt * 256;
        __syncthreads();
        for (int idx = tid; idx < V * 256; idx += 256) {
            int v = idx >> 8, kk = idx & 255;
            s_emb[v][kk] = __ldg(&emb[v * H + k0 + kk]);
        }
        __syncthreads();
        const float4* Wr = reinterpret_cast<const float4*>(Wih + (size_t)row * H + k0);
#pragma unroll
        for (int it = 0; it < 2; it++) {
            const int kl = it * 32 + lane;
            float4 w4 = __ldg(&Wr[kl]);
#pragma unroll
            for (int v = 0; v < V; v++) {
                float4 e = reinterpret_cast<const float4*>(s_emb[v])[kl];
                acc[v] += w4.x * e.x + w4.y * e.y + w4.z * e.z + w4.w * e.w;
            }
        }
    }

    float bias = 0.0f;
#pragma unroll
    for (int v = 0; v < V; v++) {
        float s = warpsum(acc[v]);
        if (lane == 0) {
            if (v == 0) bias = __ldg(&bih[row]) + __ldg(&bhh[row]);
            g_table[(size_t)which * V * G4 + (size_t)v * G4 + row] = s + bias;
        }
    }
}

// ---------------------------------------------------------------------------
// Persistent LSTM kernel. 148 CTAs x 1024 threads. Structure = round 5
// (measured best): counter barrier, h staged through smem, 49 SMEM weight
// rows + 7 L2-streamed. NEW: weights are biased-u16, dequantized with PRMT
// magic-number assembly (alu pipe) instead of I2F (conversion pipe), with a
// single per-row FMA correction  acc -= K * sum(h_slice).
// ---------------------------------------------------------------------------
__global__ __launch_bounds__(1024, 1) void k_main(
    const int*   __restrict__ x,      const int*   __restrict__ target,
    const float* __restrict__ eps,
    const float* __restrict__ mu_W,    const float* __restrict__ mu_b,
    const float* __restrict__ lv_W,    const float* __restrict__ lv_b,
    float* __restrict__ out)
{
    extern __shared__ __align__(16) unsigned s_dyn[];
    unsigned* s_w     = s_dyn + OFF_W;               // [49][1024] u32 (2 u16)
    float*    s_h     = (float*)(s_dyn + OFF_H);     // [2048]
    float*    s_part  = (float*)(s_dyn + OFF_PART);  // [56][4]
    float*    s_gates = (float*)(s_dyn + OFF_GATES); // [56]
    float*    s_c     = (float*)(s_dyn + OFF_C);     // [14]

    const int tid = threadIdx.x, lane = tid & 31, w = tid >> 5;
    const int g = w >> 2;        // row-group 0..7
    const int q = w & 3;         // k-slice 0..3
    const int j0 = blockIdx.x * CPB;
    int nloc = H - j0;
    if (nloc > CPB) nloc = CPB;
    if (nloc < 0)  nloc = 0;
    const int nrows = nloc * 4;

    if (tid < CPB) s_c[tid] = 0.0f;

    int rb = 0;

    for (int phase = 0; phase < 2; phase++) {
        const unsigned short* Wq = g_Wq[phase];
        const float* wsc   = g_wscale[phase];
        const float* table = g_table + (size_t)phase * V * G4;

        // ---- load the 49 SMEM-resident weight rows for this phase ----
        __syncthreads();
        {
            const unsigned* Wq32 = reinterpret_cast<const unsigned*>(Wq);
            for (int sidx = 0; sidx < 49; sidx++) {
                int lr = (sidx < 48) ? ((sidx / 6) + 8 * (sidx % 6)) : 48;
                if (lr < nrows) {
                    const int row = (lr & 3) * H + j0 + (lr >> 2);
                    s_w[sidx * 1024 + tid] = __ldg(&Wq32[(size_t)row * 1024 + tid]);
                }
            }
        }
        __syncthreads();

        for (int t = 0; t < T; t++) {
            // prefetch streamed row (one per group, g>=1)
            const int lrs = 48 + g;
            const bool do_stream = (g >= 1) && (lrs < nrows);
            uint2 pf[4];
            if (do_stream) {
                const int row = (lrs & 3) * H + j0 + (lrs >> 2);
                const uint2* gw = reinterpret_cast<const uint2*>(
                    Wq + (size_t)row * H) + q * 128 + lane;
#pragma unroll
                for (int c = 0; c < 4; c++) pf[c] = __ldg(&gw[c * 32]);
            }

            // broadcast full h into smem (one L2 read per line per CTA)
            for (int j = tid; j < H; j += 1024) s_h[j] = __ldcg(&g_h[rb][j]);
            __syncthreads();

            // per-warp h-slice in registers: k = q*512 + c*128 + lane*4
            const float4* sh4 = reinterpret_cast<const float4*>(s_h);
            float4 hv[4];
            float hsum = 0.0f;
#pragma unroll
            for (int c = 0; c < 4; c++) {
                hv[c] = sh4[q * 128 + c * 32 + lane];
                hsum += (hv[c].x + hv[c].y) + (hv[c].z + hv[c].w);
            }

            // SMEM rows: k = 0..5 (all g), plus k=6 for g==0
            const int kmax = (g == 0) ? 7 : 6;
#pragma unroll
            for (int k = 0; k < 7; k++) {
                if (k >= kmax) break;
                const int lr = g + 8 * k;
                if (lr < nrows) {
                    const int sidx = (k < 6) ? (g * 6 + k) : 48;
                    const uint2* wp = reinterpret_cast<const uint2*>(s_w) +
                                      (size_t)sidx * 512 + q * 128 + lane;
                    float acc = 0.0f;
#pragma unroll
                    for (int c = 0; c < 4; c++) {
                        uint2 ab = wp[c * 32];
                        acc = fmaf(CVT_LO(ab.x), hv[c].x, acc);
                        acc = fmaf(CVT_HI(ab.x), hv[c].y, acc);
                        acc = fmaf(CVT_LO(ab.y), hv[c].z, acc);
                        acc = fmaf(CVT_HI(ab.y), hv[c].w, acc);
                    }
                    acc = fmaf(-KMAGIC, hsum, acc);   // remove bias term
                    acc = warpsum(acc);
                    if (lane == 0) s_part[lr * 4 + q] = acc;
                }
            }
            if (do_stream) {
                float acc = 0.0f;
#pragma unroll
                for (int c = 0; c < 4; c++) {
                    acc = fmaf(CVT_LO(pf[c].x), hv[c].x, acc);
                    acc = fmaf(CVT_HI(pf[c].x), hv[c].y, acc);
                    acc = fmaf(CVT_LO(pf[c].y), hv[c].z, acc);
                    acc = fmaf(CVT_HI(pf[c].y), hv[c].w, acc);
                }
                acc = fmaf(-KMAGIC, hsum, acc);
                acc = warpsum(acc);
                if (lane == 0) s_part[lrs * 4 + q] = acc;
            }
            __syncthreads();

            // combine 4 slice-partials, dequant, add table
            if (tid < nrows) {
                const int tok = (phase == 0) ? __ldg(&x[t])
                                             : (t == 0 ? 0 : __ldg(&target[t - 1]));
                const int row = (tid & 3) * H + j0 + (tid >> 2);
                float s = (s_part[tid * 4 + 0] + s_part[tid * 4 + 1]) +
                          (s_part[tid * 4 + 2] + s_part[tid * 4 + 3]);
                s_gates[tid] = s * __ldg(&wsc[row]) +
                               __ldg(&table[(size_t)tok * G4 + row]);
            }
            __syncthreads();

            if (tid < nloc) {
                const float gi = s_gates[tid * 4 + 0];
                const float gf = s_gates[tid * 4 + 1];
                const float gg = s_gates[tid * 4 + 2];
                const float go = s_gates[tid * 4 + 3];
                float c = sigm(gf) * s_c[tid] + sigm(gi) * tanhf(gg);
                s_c[tid] = c;
                float h = sigm(go) * tanhf(c);
                __stcg(&g_h[rb ^ 1][j0 + tid], h);
                if (phase)
                    out[512 + (size_t)t * H + j0 + tid] = h;
            }
            __threadfence();
            grid_sync();
            rb ^= 1;
        }

        if (phase == 0) {
            // VAE heads: mu, logvar from h_enc (in g_h[rb]); z -> g_h[rb^1]
            for (int j = tid; j < H; j += 1024) s_h[j] = __ldcg(&g_h[rb][j]);
            __syncthreads();
            const float4* sh4 = reinterpret_cast<const float4*>(s_h);
            if (w < nloc * 2) {
                const int l = w >> 1, m = w & 1;
                const float* Wm = m ? lv_W : mu_W;
                const int row = j0 + l;
                const float4* W4 = reinterpret_cast<const float4*>(Wm) +
                                   (size_t)row * (H / 4);
                float s = 0.0f;
#pragma unroll 8
                for (int i = lane; i < H / 4; i += 32) {
                    float4 a = __ldg(&W4[i]);
                    float4 b = sh4[i];
                    s += a.x * b.x + a.y * b.y + a.z * b.z + a.w * b.w;
                }
                s = warpsum(s);
                if (lane == 0)
                    s_gates[w] = s + __ldg(&(m ? lv_b : mu_b)[row]);
            }
            __syncthreads();
            if (tid < nloc) {
                const int j = j0 + tid;
                const float mu = s_gates[tid * 2 + 0];
                const float lv = s_gates[tid * 2 + 1];
                out[512 + (size_t)T * H + j]     = mu;
                out[512 + (size_t)T * H + H + j] = lv;
                float z = mu + __ldg(&eps[j]) * expf(0.5f * lv);
                __stcg(&g_h[rb ^ 1][j], z);
            }
            __threadfence();
            grid_sync();
            rb ^= 1;
        }
    }
}

// ---------------------------------------------------------------------------
// Argmax over hidden dim of each decoder output row (first-index tie-break).
// ---------------------------------------------------------------------------
__global__ __launch_bounds__(256) void k_argmax(float* __restrict__ out)
{
    __shared__ float sv[256];
    __shared__ int   si[256];
    const int t = blockIdx.x;
    const float* row = out + 512 + (size_t)t * H;
    float best = -3.402823466e+38f;
    int   bi = 0;
    for (int j = threadIdx.x; j < H; j += 256) {
        float v = row[j];
        if (v > best) { best = v; bi = j; }
    }
    sv[threadIdx.x] = best;
    si[threadIdx.x] = bi;
    __syncthreads();
    for (int s = 128; s; s >>= 1) {
        if (threadIdx.x < s) {
            float ov = sv[threadIdx.x + s];
            int   oi = si[threadIdx.x + s];
            if (ov > sv[threadIdx.x] ||
                (ov == sv[threadIdx.x] && oi < si[threadIdx.x])) {
                sv[threadIdx.x] = ov;
                si[threadIdx.x] = oi;
            }
        }
        __syncthreads();
    }
    if (threadIdx.x == 0) out[t] = (float)si[0];
}

// ---------------------------------------------------------------------------
extern "C" void kernel_launch(void* const* d_in, const int* in_sizes, int n_in,
                              void* d_out, int out_size)
{
    const int*   x       = (const int*)  d_in[0];
    const int*   target  = (const int*)  d_in[1];
    const float* eps     = (const float*)d_in[2];
    const float* enc_emb = (const float*)d_in[3];
    const float* enc_Wih = (const float*)d_in[4];
    const float* enc_Whh = (const float*)d_in[5];
    const float* enc_bih = (const float*)d_in[6];
    const float* enc_bhh = (const float*)d_in[7];
    const float* mu_W    = (const float*)d_in[8];
    const float* mu_b    = (const float*)d_in[9];
    const float* lv_W    = (const float*)d_in[10];
    const float* lv_b    = (const float*)d_in[11];
    const float* dec_emb = (const float*)d_in[12];
    const float* dec_Wih = (const float*)d_in[13];
    const float* dec_Whh = (const float*)d_in[14];
    const float* dec_bih = (const float*)d_in[15];
    const float* dec_bhh = (const float*)d_in[16];
    float* out = (float*)d_out;

    cudaFuncSetAttribute(k_main, cudaFuncAttributeMaxDynamicSharedMemorySize,
                         SMEM_BYTES);

    k_pre<<<2048, 256>>>(enc_emb, enc_Wih, enc_bih, enc_bhh,
                         dec_emb, dec_Wih, dec_bih, dec_bhh);
    k_quant<<<2 * G4, 256>>>(enc_Whh, dec_Whh);
    k_main<<<NCTA, 1024, SMEM_BYTES>>>(x, target, eps,
                                       mu_W, mu_b, lv_W, lv_b, out);
    k_argmax<<<512, 256>>>(out);
}

// round 9
// speedup vs baseline: 2.0899x; 1.1507x over previous
#include <cuda_runtime.h>
#include <cuda_bf16.h>

#define H     2048
#define G4    8192          // 4*H gate rows
#define V     28
#define T     512
#define NCTA  148
#define CPB   14            // h-indices per CTA
#define ROWS  56            // gate rows per CTA
#define SMEM_ROWS 49        // rows resident in SMEM; rest (7) stream from L2
#define WMAT  16777216      // G4*H elements per matrix
#define KMAGIC 8421376.0f   // 2^23 + 32768 (biased-u16 float offset)

// dynamic smem layout (u32 units)
#define OFF_W     0
#define OFF_H     (SMEM_ROWS * 1024)            // 50176
#define OFF_PART  (OFF_H + 2048)                // 52224  : 56 rows x 4 slices
#define OFF_C     (OFF_PART + ROWS * 4)         // 52448
#define SMEM_U32  (OFF_C + CPB)                 // 52462
#define SMEM_BYTES (SMEM_U32 * 4)

// ---- device scratch (no allocations allowed) ----
__device__ float          g_table[2u * V * G4]; // [enc/dec][vocab][4H] gate table
__device__ unsigned short g_Wq[2][WMAT];        // biased-u16 quantized Whh
__device__ float          g_wscale[2][G4];      // per-row dequant scales
__device__ float          g_h[2][H];            // double-buffered hidden state
__device__ unsigned       g_bar_count = 0;
__device__ unsigned       g_bar_phase = 0;

__device__ __forceinline__ float warpsum(float v) {
#pragma unroll
    for (int o = 16; o; o >>= 1) v += __shfl_xor_sync(0xffffffffu, v, o);
    return v;
}
__device__ __forceinline__ float sigm(float x) { return 1.0f / (1.0f + expf(-x)); }

// Counter grid barrier (measured best across rounds 3-7). The release fence
// is issued by tid 0 ONLY: the entry __syncthreads() gives intra-CTA HB from
// the h-writers to tid 0, and fence cumulativity makes their stores visible
// before the arrival atomic. No caller-side fence needed.
__device__ __forceinline__ void grid_sync() {
    __syncthreads();
    if (threadIdx.x == 0) {
        volatile unsigned* ph = &g_bar_phase;
        unsigned p = *ph;
        __threadfence();                       // release (cumulative)
        unsigned arr = atomicAdd(&g_bar_count, 1u);
        if (arr == NCTA - 1u) {
            g_bar_count = 0u;
            __threadfence();
            atomicAdd(&g_bar_phase, 1u);
        } else {
            while (*ph == p) { }
            __threadfence();                   // acquire
        }
    }
    __syncthreads();
}

// biased-u16 pair -> 2 fp32 (value = 2^23 + biased) via PRMT; no I2F.
#define CVT_LO(u) __uint_as_float(__byte_perm((u), 0x4B000000u, 0x7410))
#define CVT_HI(u) __uint_as_float(__byte_perm((u), 0x4B000000u, 0x7432))

// ---------------------------------------------------------------------------
// Quantize Whh rows to biased uint16 with per-row fp32 scale.
// ---------------------------------------------------------------------------
__global__ __launch_bounds__(256) void k_quant(
    const float* __restrict__ encW, const float* __restrict__ decW)
{
    __shared__ float s_max[8];
    const int r     = blockIdx.x;       // 0..16383
    const int which = r >> 13;
    const int row   = r & (G4 - 1);
    const int tid = threadIdx.x, lane = tid & 31, w = tid >> 5;

    const float4* W4 = reinterpret_cast<const float4*>(
        (which ? decW : encW) + (size_t)row * H);

    float4 v0 = __ldg(&W4[tid]);
    float4 v1 = __ldg(&W4[tid + 256]);

    float m = fmaxf(fmaxf(fabsf(v0.x), fabsf(v0.y)), fmaxf(fabsf(v0.z), fabsf(v0.w)));
    m = fmaxf(m, fmaxf(fmaxf(fabsf(v1.x), fabsf(v1.y)), fmaxf(fabsf(v1.z), fabsf(v1.w))));
#pragma unroll
    for (int o = 16; o; o >>= 1) m = fmaxf(m, __shfl_xor_sync(0xffffffffu, m, o));
    if (lane == 0) s_max[w] = m;
    __syncthreads();
    if (tid == 0) {
        float mm = s_max[0];
#pragma unroll
        for (int i = 1; i < 8; i++) mm = fmaxf(mm, s_max[i]);
        s_max[0] = mm;
        g_wscale[which][row] = mm * (1.0f / 32766.0f);
    }
    __syncthreads();
    const float mv  = s_max[0];
    const float inv = (mv > 0.0f) ? (32766.0f / mv) : 0.0f;

    ushort4* Q4 = reinterpret_cast<ushort4*>(&g_Wq[which][(size_t)row * H]);
    ushort4 q;
    q.x = (unsigned short)(__float2int_rn(v0.x * inv) + 32768);
    q.y = (unsigned short)(__float2int_rn(v0.y * inv) + 32768);
    q.z = (unsigned short)(__float2int_rn(v0.z * inv) + 32768);
    q.w = (unsigned short)(__float2int_rn(v0.w * inv) + 32768);
    Q4[tid] = q;
    q.x = (unsigned short)(__float2int_rn(v1.x * inv) + 32768);
    q.y = (unsigned short)(__float2int_rn(v1.y * inv) + 32768);
    q.z = (unsigned short)(__float2int_rn(v1.z * inv) + 32768);
    q.w = (unsigned short)(__float2int_rn(v1.w * inv) + 32768);
    Q4[tid + 256] = q;
}

// ---------------------------------------------------------------------------
// Precompute per-vocab gate tables; block 0 also zeroes g_h[0].
// ---------------------------------------------------------------------------
__global__ __launch_bounds__(256) void k_pre(
    const float* __restrict__ enc_emb, const float* __restrict__ enc_Wih,
    const float* __restrict__ enc_bih, const float* __restrict__ enc_bhh,
    const float* __restrict__ dec_emb, const float* __restrict__ dec_Wih,
    const float* __restrict__ dec_bih, const float* __restrict__ dec_bhh)
{
    __shared__ __align__(16) float s_emb[V][256];
    const int tid = threadIdx.x, lane = tid & 31, warp = tid >> 5;

    if (blockIdx.x == 0) {
        for (int j = tid; j < H; j += 256) g_h[0][j] = 0.0f;
    }

    const int   which = (blockIdx.x >= 1024) ? 1 : 0;
    const float* emb = which ? dec_emb : enc_emb;
    const float* Wih = which ? dec_Wih : enc_Wih;
    const float* bih = which ? dec_bih : enc_bih;
    const float* bhh = which ? dec_bhh : enc_bhh;
    const int row = (blockIdx.x & 1023) * 8 + warp;   // 0..8191

    float acc[V];
#pragma unroll
    for (int v = 0; v < V; v++) acc[v] = 0.0f;

    for (int kt = 0; kt < 8; kt++) {
        const int k0 = kt * 256;
        __syncthreads();
        for (int idx = tid; idx < V * 256; idx += 256) {
            int v = idx >> 8, kk = idx & 255;
            s_emb[v][kk] = __ldg(&emb[v * H + k0 + kk]);
        }
        __syncthreads();
        const float4* Wr = reinterpret_cast<const float4*>(Wih + (size_t)row * H + k0);
#pragma unroll
        for (int it = 0; it < 2; it++) {
            const int kl = it * 32 + lane;
            float4 w4 = __ldg(&Wr[kl]);
#pragma unroll
            for (int v = 0; v < V; v++) {
                float4 e = reinterpret_cast<const float4*>(s_emb[v])[kl];
                acc[v] += w4.x * e.x + w4.y * e.y + w4.z * e.z + w4.w * e.w;
            }
        }
    }

    float bias = 0.0f;
#pragma unroll
    for (int v = 0; v < V; v++) {
        float s = warpsum(acc[v]);
        if (lane == 0) {
            if (v == 0) bias = __ldg(&bih[row]) + __ldg(&bhh[row]);
            g_table[(size_t)which * V * G4 + (size_t)v * G4 + row] = s + bias;
        }
    }
}

// ---------------------------------------------------------------------------
// Persistent LSTM kernel. 148 CTAs x 1024 threads. R8 structure with three
// cuts: (1) no caller-side all-thread threadfence (tid0 fence in grid_sync
// suffices), (2) combine+cell fused into the 14 owner threads (one fewer
// __syncthreads + no s_gates round trip), (3) h broadcast as one float2
// load per thread.
// ---------------------------------------------------------------------------
__global__ __launch_bounds__(1024, 1) void k_main(
    const int*   __restrict__ x,      const int*   __restrict__ target,
    const float* __restrict__ eps,
    const float* __restrict__ mu_W,    const float* __restrict__ mu_b,
    const float* __restrict__ lv_W,    const float* __restrict__ lv_b,
    float* __restrict__ out)
{
    extern __shared__ __align__(16) unsigned s_dyn[];
    unsigned* s_w     = s_dyn + OFF_W;               // [49][1024] u32 (2 u16)
    float*    s_h     = (float*)(s_dyn + OFF_H);     // [2048]
    float*    s_part  = (float*)(s_dyn + OFF_PART);  // [56][4]
    float*    s_c     = (float*)(s_dyn + OFF_C);     // [14]

    const int tid = threadIdx.x, lane = tid & 31, w = tid >> 5;
    const int g = w >> 2;        // row-group 0..7
    const int q = w & 3;         // k-slice 0..3
    const int j0 = blockIdx.x * CPB;
    int nloc = H - j0;
    if (nloc > CPB) nloc = CPB;
    if (nloc < 0)  nloc = 0;
    const int nrows = nloc * 4;

    if (tid < CPB) s_c[tid] = 0.0f;

    int rb = 0;

    for (int phase = 0; phase < 2; phase++) {
        const unsigned short* Wq = g_Wq[phase];
        const float* wsc   = g_wscale[phase];
        const float* table = g_table + (size_t)phase * V * G4;

        // ---- load the 49 SMEM-resident weight rows for this phase ----
        __syncthreads();
        {
            const unsigned* Wq32 = reinterpret_cast<const unsigned*>(Wq);
            for (int sidx = 0; sidx < 49; sidx++) {
                int lr = (sidx < 48) ? ((sidx / 6) + 8 * (sidx % 6)) : 48;
                if (lr < nrows) {
                    const int row = (lr & 3) * H + j0 + (lr >> 2);
                    s_w[sidx * 1024 + tid] = __ldg(&Wq32[(size_t)row * 1024 + tid]);
                }
            }
        }
        __syncthreads();

        for (int t = 0; t < T; t++) {
            // prefetch streamed row (one per group, g>=1)
            const int lrs = 48 + g;
            const bool do_stream = (g >= 1) && (lrs < nrows);
            uint2 pf[4];
            if (do_stream) {
                const int row = (lrs & 3) * H + j0 + (lrs >> 2);
                const uint2* gw = reinterpret_cast<const uint2*>(
                    Wq + (size_t)row * H) + q * 128 + lane;
#pragma unroll
                for (int c = 0; c < 4; c++) pf[c] = __ldg(&gw[c * 32]);
            }

            // broadcast full h into smem: one float2 per thread
            {
                float2 hv2 = __ldcg(&reinterpret_cast<const float2*>(g_h[rb])[tid]);
                reinterpret_cast<float2*>(s_h)[tid] = hv2;
            }
            __syncthreads();

            // per-warp h-slice in registers: k = q*512 + c*128 + lane*4
            const float4* sh4 = reinterpret_cast<const float4*>(s_h);
            float4 hv[4];
            float hsum = 0.0f;
#pragma unroll
            for (int c = 0; c < 4; c++) {
                hv[c] = sh4[q * 128 + c * 32 + lane];
                hsum += (hv[c].x + hv[c].y) + (hv[c].z + hv[c].w);
            }

            // SMEM rows: k = 0..5 (all g), plus k=6 for g==0
            const int kmax = (g == 0) ? 7 : 6;
#pragma unroll
            for (int k = 0; k < 7; k++) {
                if (k >= kmax) break;
                const int lr = g + 8 * k;
                if (lr < nrows) {
                    const int sidx = (k < 6) ? (g * 6 + k) : 48;
                    const uint2* wp = reinterpret_cast<const uint2*>(s_w) +
                                      (size_t)sidx * 512 + q * 128 + lane;
                    float acc = 0.0f;
#pragma unroll
                    for (int c = 0; c < 4; c++) {
                        uint2 ab = wp[c * 32];
                        acc = fmaf(CVT_LO(ab.x), hv[c].x, acc);
                        acc = fmaf(CVT_HI(ab.x), hv[c].y, acc);
                        acc = fmaf(CVT_LO(ab.y), hv[c].z, acc);
                        acc = fmaf(CVT_HI(ab.y), hv[c].w, acc);
                    }
                    acc = fmaf(-KMAGIC, hsum, acc);   // remove bias term
                    acc = warpsum(acc);
                    if (lane == 0) s_part[lr * 4 + q] = acc;
                }
            }
            if (do_stream) {
                float acc = 0.0f;
#pragma unroll
                for (int c = 0; c < 4; c++) {
                    acc = fmaf(CVT_LO(pf[c].x), hv[c].x, acc);
                    acc = fmaf(CVT_HI(pf[c].x), hv[c].y, acc);
                    acc = fmaf(CVT_LO(pf[c].y), hv[c].z, acc);
                    acc = fmaf(CVT_HI(pf[c].y), hv[c].w, acc);
                }
                acc = fmaf(-KMAGIC, hsum, acc);
                acc = warpsum(acc);
                if (lane == 0) s_part[lrs * 4 + q] = acc;
            }
            __syncthreads();

            // fused combine + dequant + table + cell update (owner threads)
            if (tid < nloc) {
                const int tok = (phase == 0) ? __ldg(&x[t])
                                             : (t == 0 ? 0 : __ldg(&target[t - 1]));
                float gate[4];
#pragma unroll
                for (int ga = 0; ga < 4; ga++) {
                    const int lr = tid * 4 + ga;
                    const int row = ga * H + j0 + tid;
                    float s = (s_part[lr * 4 + 0] + s_part[lr * 4 + 1]) +
                              (s_part[lr * 4 + 2] + s_part[lr * 4 + 3]);
                    gate[ga] = s * __ldg(&wsc[row]) +
                               __ldg(&table[(size_t)tok * G4 + row]);
                }
                float c = sigm(gate[1]) * s_c[tid] + sigm(gate[0]) * tanhf(gate[2]);
                s_c[tid] = c;
                float h = sigm(gate[3]) * tanhf(c);
                __stcg(&g_h[rb ^ 1][j0 + tid], h);
                if (phase)
                    out[512 + (size_t)t * H + j0 + tid] = h;
            }
            grid_sync();           // tid0-only release fence inside
            rb ^= 1;
        }

        if (phase == 0) {
            // VAE heads: mu, logvar from h_enc (in g_h[rb]); z -> g_h[rb^1]
            {
                float2 hv2 = __ldcg(&reinterpret_cast<const float2*>(g_h[rb])[tid]);
                reinterpret_cast<float2*>(s_h)[tid] = hv2;
            }
            __syncthreads();
            const float4* sh4 = reinterpret_cast<const float4*>(s_h);
            if (w < nloc * 2) {
                const int l = w >> 1, m = w & 1;
                const float* Wm = m ? lv_W : mu_W;
                const int row = j0 + l;
                const float4* W4 = reinterpret_cast<const float4*>(Wm) +
                                   (size_t)row * (H / 4);
                float s = 0.0f;
#pragma unroll 8
                for (int i = lane; i < H / 4; i += 32) {
                    float4 a = __ldg(&W4[i]);
                    float4 b = sh4[i];
                    s += a.x * b.x + a.y * b.y + a.z * b.z + a.w * b.w;
                }
                s = warpsum(s);
                if (lane == 0)
                    s_part[w] = s + __ldg(&(m ? lv_b : mu_b)[row]);
            }
            __syncthreads();
            if (tid < nloc) {
                const int j = j0 + tid;
                const float mu = s_part[tid * 2 + 0];
                const float lv = s_part[tid * 2 + 1];
                out[512 + (size_t)T * H + j]     = mu;
                out[512 + (size_t)T * H + H + j] = lv;
                float z = mu + __ldg(&eps[j]) * expf(0.5f * lv);
                __stcg(&g_h[rb ^ 1][j], z);
            }
            grid_sync();
            rb ^= 1;
        }
    }
}

// ---------------------------------------------------------------------------
// Argmax over hidden dim of each decoder output row (first-index tie-break).
// ---------------------------------------------------------------------------
__global__ __launch_bounds__(256) void k_argmax(float* __restrict__ out)
{
    __shared__ float sv[256];
    __shared__ int   si[256];
    const int t = blockIdx.x;
    const float* row = out + 512 + (size_t)t * H;
    float best = -3.402823466e+38f;
    int   bi = 0;
    for (int j = threadIdx.x; j < H; j += 256) {
        float v = row[j];
        if (v > best) { best = v; bi = j; }
    }
    sv[threadIdx.x] = best;
    si[threadIdx.x] = bi;
    __syncthreads();
    for (int s = 128; s; s >>= 1) {
        if (threadIdx.x < s) {
            float ov = sv[threadIdx.x + s];
            int   oi = si[threadIdx.x + s];
            if (ov > sv[threadIdx.x] ||
                (ov == sv[threadIdx.x] && oi < si[threadIdx.x])) {
                sv[threadIdx.x] = ov;
                si[threadIdx.x] = oi;
            }
        }
        __syncthreads();
    }
    if (threadIdx.x == 0) out[t] = (float)si[0];
}

// ---------------------------------------------------------------------------
extern "C" void kernel_launch(void* const* d_in, const int* in_sizes, int n_in,
                              void* d_out, int out_size)
{
    const int*   x       = (const int*)  d_in[0];
    const int*   target  = (const int*)  d_in[1];
    const float* eps     = (const float*)d_in[2];
    const float* enc_emb = (const float*)d_in[3];
    const float* enc_Wih = (const float*)d_in[4];
    const float* enc_Whh = (const float*)d_in[5];
    const float* enc_bih = (const float*)d_in[6];
    const float* enc_bhh = (const float*)d_in[7];
    const float* mu_W    = (const float*)d_in[8];
    const float* mu_b    = (const float*)d_in[9];
    const float* lv_W    = (const float*)d_in[10];
    const float* lv_b    = (const float*)d_in[11];
    const float* dec_emb = (const float*)d_in[12];
    const float* dec_Wih = (const float*)d_in[13];
    const float* dec_Whh = (const float*)d_in[14];
    const float* dec_bih = (const float*)d_in[15];
    const float* dec_bhh = (const float*)d_in[16];
    float* out = (float*)d_out;

    cudaFuncSetAttribute(k_main, cudaFuncAttributeMaxDynamicSharedMemorySize,
                         SMEM_BYTES);

    k_pre<<<2048, 256>>>(enc_emb, enc_Wih, enc_bih, enc_bhh,
                         dec_emb, dec_Wih, dec_bih, dec_bhh);
    k_quant<<<2 * G4, 256>>>(enc_Whh, dec_Whh);
    k_main<<<NCTA, 1024, SMEM_BYTES>>>(x, target, eps,
                                       mu_W, mu_b, lv_W, lv_b, out);
    k_argmax<<<512, 256>>>(out);
}